// round 11
// baseline (speedup 1.0000x reference)
#include <cuda_runtime.h>

#define S_LEN 4096
#define D_DIM 300
#define H_DIM 300
#define HU    150
#define G4    600   // 4*HU

// ---------------- scratch (static device globals; no allocation) ----------------
__device__ float g_xW[2][S_LEN * G4];        // x@W + b, per direction (bwd pre-reversed)
__device__ float g_hidden[S_LEN * H_DIM];    // [S,300]: cols 0..149 fwd, 150..299 bwd
__device__ float g_attout[S_LEN * H_DIM];    // hidden @ W_p + b_p
__device__ float g_m[S_LEN * D_DIM];         // attention m vectors
__device__ float g_coeff[S_LEN];             // secondary attention coeffs
__device__ float g_partial[64 * G4];         // deterministic reduction partials

// ---------------- helpers ----------------
__device__ __forceinline__ unsigned long long ffma2(unsigned long long a,
                                                    unsigned long long b,
                                                    unsigned long long c) {
    unsigned long long d;
    asm("fma.rn.f32x2 %0, %1, %2, %3;" : "=l"(d) : "l"(a), "l"(b), "l"(c));
    return d;
}
__device__ __forceinline__ unsigned long long pack2(float lo, float hi) {
    unsigned long long p;
    asm("mov.b64 %0, {%1, %2};" : "=l"(p) : "f"(lo), "f"(hi));
    return p;
}
__device__ __forceinline__ void unpack2(unsigned long long v, float& lo, float& hi) {
    asm("mov.b64 {%0, %1}, %2;" : "=f"(lo), "=f"(hi) : "l"(v));
}
__device__ __forceinline__ void cluster_sync_() {
    asm volatile("barrier.cluster.arrive.aligned;" ::: "memory");
    asm volatile("barrier.cluster.wait.aligned;" ::: "memory");
}
__device__ __forceinline__ float ex2f_(float x) {
    float y; asm("ex2.approx.f32 %0, %1;" : "=f"(y) : "f"(x)); return y;
}
__device__ __forceinline__ float rcpf_(float x) {
    float y; asm("rcp.approx.f32 %0, %1;" : "=f"(y) : "f"(x)); return y;
}
// sigmoid via ex2/rcp approx: rel err ~1e-7 (far inside 1e-3 budget)
__device__ __forceinline__ float sigmoid_fast(float x) {
    return rcpf_(1.0f + ex2f_(-1.4426950408889634f * x));
}
__device__ __forceinline__ float tanh_fast(float x) {
    return fmaf(2.0f, sigmoid_fast(2.0f * x), -1.0f);
}

// ---------------- K0: no-op (keeps ncu's capture window on lstm_kernel) ----------------
__global__ void dummy_kernel() {}

// ---------------- K1: xW = gather(emb) @ W_dir + b_dir (bwd rows pre-reversed) ----------------
__global__ __launch_bounds__(608, 2)
void xw_kernel(const int* __restrict__ sent, const float* __restrict__ E,
               const float* __restrict__ W_f, const float* __restrict__ b_f,
               const float* __restrict__ W_b, const float* __restrict__ b_b) {
    const int dir = blockIdx.y;
    const int s0  = blockIdx.x * 16;
    const float* __restrict__ W  = dir ? W_b : W_f;
    const float* __restrict__ bv = dir ? b_b : b_f;
    __shared__ float esm[16 * D_DIM];
    const int tid = threadIdx.x;
    for (int i = tid; i < 16 * D_DIM; i += 608) {
        int r = i / D_DIM, k = i - r * D_DIM;
        int srow = dir ? (S_LEN - 1 - (s0 + r)) : (s0 + r);
        esm[i] = E[(long long)sent[srow] * D_DIM + k];
    }
    __syncthreads();
    const int j = tid;
    if (j < G4) {
        float acc[16];
#pragma unroll
        for (int r = 0; r < 16; r++) acc[r] = 0.f;
        for (int k = 0; k < D_DIM; k++) {
            float w = W[k * G4 + j];
#pragma unroll
            for (int r = 0; r < 16; r++) acc[r] = fmaf(esm[r * D_DIM + k], w, acc[r]);
        }
        float bb = bv[j];
#pragma unroll
        for (int r = 0; r < 16; r++) g_xW[dir][(s0 + r) * G4 + j] = acc[r] + bb;
    }
}

// ---------------- K2: persistent biLSTM. 2 clusters of 2 CTAs (one cluster/dir). ----------------
// 608 threads: thread = (cell mloc=tid>>3, gate g=(tid>>1)&3, K-half hf=tid&1); 38 u64 of U each.
// Step order hides the ~215cyc DSMEM flight:
//   (A) own-half dot over own_h[p]  (hf0 lanes; local data)   <- peer packet in flight here
//   (B) checkers spin on {h,tag} packets (landed by now), stage; bar#1
//   (C) peer-half dot over stage[p] (hf1 lanes); combine; act; writer tail; bar#2
// Exchange = one weak 8B st.shared::cluster per cell (single-copy atomic, fire-and-forget).
__global__ void __cluster_dims__(2, 1, 1) __launch_bounds__(608, 1)
lstm_kernel(const float* __restrict__ U_f, const float* __restrict__ U_b) {
    const int dir = blockIdx.x >> 1;
    unsigned rank; asm("mov.u32 %0, %%cluster_ctarank;" : "=r"(rank));
    const int tid = threadIdx.x;
    const float* __restrict__ U  = dir ? U_b : U_f;
    const float* __restrict__ xW = g_xW[dir];

    __shared__ __align__(16) float own_h[2][76];               // local h, slot 75 = pad
    __shared__ __align__(16) float stage[2][76];               // validated peer h values
    __shared__ __align__(8)  unsigned long long pkt[2][76];    // {val lo32, tag hi32}, remote-written

    for (int i = tid; i < 152; i += 608) ((float*)own_h)[i] = 0.f;
    for (int i = tid; i < 152; i += 608) ((float*)stage)[i] = 0.f;
    for (int i = tid; i < 76; i += 608) {
        pkt[0][i] = 0xFFFFFFFF00000000ull;   // tag -1, val 0 (consumed at t=0)
        pkt[1][i] = 0xFFFFFFFE00000000ull;   // tag -2 (never matches until written)
    }
    __syncthreads();

    const bool active = tid < 600;
    const int hf   = tid & 1;                   // K-half: 0 = own cells, 1 = peer cells
    const int g    = (tid >> 1) & 3;            // gate i,f,g,o
    const int mloc = tid >> 3;                  // 0..74 when active
    const int m    = (int)rank * 75 + (active ? mloc : 0);
    const int j    = g * HU + m;                // column in [0,600)
    const int prank = 1 - (int)rank;
    const int hb   = hf ? prank * 75 : (int)rank * 75;   // U row base for this half

    // 38 u64 of U for this thread's K-half (pad pair index 75 -> zero weight)
    unsigned long long u64[38];
#pragma unroll
    for (int s = 0; s < 38; s++) {
        int k0 = 2 * s, k1 = 2 * s + 1;
        float w0 = (active && k0 < 75) ? U[(hb + k0) * G4 + j] : 0.f;
        float w1 = (active && k1 < 75) ? U[(hb + k1) * G4 + j] : 0.f;
        u64[s] = pack2(w0, w1);
    }

    // addresses: local pkt (for checker spin) and remote pkt in peer CTA (for writer push)
    unsigned pk_base = (unsigned)__cvta_generic_to_shared(&pkt[0][0]);
    unsigned peer = rank ^ 1u;
    unsigned r_pk;
    asm("mapa.shared::cluster.u32 %0, %1, %2;" : "=r"(r_pk) : "r"(pk_base), "r"(peer));

    cluster_sync_();   // init (incl. pkt sentinels) visible cluster-wide before any writes

    float c = 0.f;
    float xw_cur = (active && hf == 0) ? xW[j] : 0.f;   // xW added once, on hf0 lane
    const bool is_checker = active && (tid & 7) == 2;
    const bool is_writer  = active && (tid & 7) == 0;

    for (int t = 0; t < S_LEN; t++) {
        const int p  = t & 1;        // read buffer
        const int nb = p ^ 1;        // write buffer

        // prefetch next xW row (hf0 lanes; consumed next step)
        float xw_next = 0.f;
        if (active && hf == 0 && t + 1 < S_LEN) xw_next = xW[(t + 1) * G4 + j];

        unsigned long long a0 = pack2(xw_cur, 0.f), a1 = 0ull;

        // (A) own-half dot over own_h[p] — runs while the peer's packets are in flight
        if (hf == 0) {
            const ulonglong2* hp = (const ulonglong2*)&own_h[p][0];
#pragma unroll
            for (int q = 0; q < 19; q++) {
                ulonglong2 v = hp[q];
                a0 = ffma2(u64[2 * q], v.x, a0);
                a1 = ffma2(u64[2 * q + 1], v.y, a1);
            }
        }

        // (B) checkers: spin until {h, tag=t-1} landed (usually already has), stage value
        if (is_checker) {
            unsigned lo, hi;
            unsigned ad = pk_base + ((unsigned)p * 76u + (unsigned)mloc) * 8u;
            const unsigned want = (unsigned)(t - 1);
            do {
                asm volatile("ld.volatile.shared.v2.u32 {%0, %1}, [%2];"
                             : "=r"(lo), "=r"(hi) : "r"(ad));
            } while (hi != want);
            stage[p][mloc] = __uint_as_float(lo);
        }
        __syncthreads();   // bar#1: publishes stage[p]

        // (C) peer-half dot over stage[p]
        if (hf == 1) {
            const ulonglong2* hp = (const ulonglong2*)&stage[p][0];
#pragma unroll
            for (int q = 0; q < 19; q++) {
                ulonglong2 v = hp[q];
                a0 = ffma2(u64[2 * q], v.x, a0);
                a1 = ffma2(u64[2 * q + 1], v.y, a1);
            }
        }
        float x0, x1, y0, y1;
        unpack2(a0, x0, x1); unpack2(a1, y0, y1);
        float zh = (x0 + x1) + (y0 + y1);

        // combine K-halves, activations, gate exchange in the aligned 8-lane cell group
        float zfull = zh + __shfl_xor_sync(0xffffffffu, zh, 1);
        float act = (g == 2) ? tanh_fast(zfull) : sigmoid_fast(zfull);
        float sf = __shfl_xor_sync(0xffffffffu, act, 2);   // writer receives f
        float sg = __shfl_xor_sync(0xffffffffu, act, 4);   // writer receives g
        float so = __shfl_xor_sync(0xffffffffu, act, 6);   // writer receives o

        if (is_writer) {
            c = fmaf(sf, c, act * sg);                     // c = f*c + i*g
            float hv = so * tanh_fast(c);
            if (t + 1 < S_LEN) {                           // remote half: ONE weak 8B store
                unsigned long long pk = ((unsigned long long)(unsigned)t << 32)
                                      | (unsigned long long)__float_as_uint(hv);
                unsigned ra = r_pk + ((unsigned)nb * 76u + (unsigned)mloc) * 8u;
                asm volatile("st.shared::cluster.u64 [%0], %1;" :: "r"(ra), "l"(pk) : "memory");
            }
            own_h[nb][mloc] = hv;                          // local half
            int row = dir ? (S_LEN - 1 - t) : t;
            g_hidden[row * H_DIM + dir * HU + m] = hv;
        }
        __syncthreads();   // bar#2: publishes own_h[nb] for next step's (A)
        xw_cur = xw_next;
    }
    cluster_sync_();   // release our last remote stores before CTA teardown
}

// ---------------- K3: attout = hidden @ W_p + b_p ----------------
__global__ __launch_bounds__(320, 2)
void attdense_kernel(const float* __restrict__ W_p, const float* __restrict__ b_p) {
    const int s0 = blockIdx.x * 16;
    __shared__ float hsm[16 * H_DIM];
    const int tid = threadIdx.x;
    for (int i = tid; i < 16 * H_DIM; i += 320) hsm[i] = g_hidden[s0 * H_DIM + i];
    __syncthreads();
    const int j = tid;
    if (j < H_DIM) {
        float acc[16];
#pragma unroll
        for (int r = 0; r < 16; r++) acc[r] = 0.f;
        for (int k = 0; k < H_DIM; k++) {
            float w = W_p[k * H_DIM + j];
#pragma unroll
            for (int r = 0; r < 16; r++) acc[r] = fmaf(hsm[r * H_DIM + k], w, acc[r]);
        }
        float bb = b_p[j];
#pragma unroll
        for (int r = 0; r < 16; r++) g_attout[(s0 + r) * H_DIM + j] = acc[r] + bb;
    }
}

// ---------------- K4: per-word synonym attention + secondary coeff ----------------
__device__ __forceinline__ float block_reduce_320(float v, float* red, int lane, int wid) {
#pragma unroll
    for (int off = 16; off; off >>= 1) v += __shfl_down_sync(0xffffffffu, v, off);
    __syncthreads();
    if (lane == 0) red[wid] = v;
    __syncthreads();
    float t = 0.f;
#pragma unroll
    for (int w = 0; w < 10; w++) t += red[w];
    return t;
}

__global__ __launch_bounds__(320)
void attn_kernel(const int* __restrict__ syn_idx, const float* __restrict__ E,
                 const float* __restrict__ W_s, const float* __restrict__ b_s) {
    const int s   = blockIdx.x;
    const int tid = threadIdx.x;
    const int lane = tid & 31, wid = tid >> 5;
    __shared__ float red[10];
    const bool active = tid < D_DIM;

    float od = 0.f, hd = 0.f;
    float ev[4] = {0.f, 0.f, 0.f, 0.f};
    if (active) {
        od = g_attout[s * H_DIM + tid];
        hd = g_hidden[s * H_DIM + tid];
#pragma unroll
        for (int k = 0; k < 4; k++)
            ev[k] = E[(long long)syn_idx[s * 4 + k] * D_DIM + tid];
    }
    float sc[4];
#pragma unroll
    for (int k = 0; k < 4; k++) {
        float dot = block_reduce_320(od * ev[k], red, lane, wid);
        sc[k] = expf(dot);
    }
    float md = sc[0] * ev[0] + sc[1] * ev[1] + sc[2] * ev[2] + sc[3] * ev[3];
    if (active) g_m[s * D_DIM + tid] = md;
    float cv = active ? (hd * W_s[tid] + md * W_s[D_DIM + tid]) : 0.f;
    float tot = block_reduce_320(cv, red, lane, wid);
    if (tid == 0) g_coeff[s] = expf(tanhf(tot + b_s[0]));
}

// ---------------- K5: deterministic partial reduction of coeff * h_hat ----------------
__global__ __launch_bounds__(608)
void reduce1_kernel() {
    const int b = blockIdx.x;
    const int j = threadIdx.x;
    if (j >= G4) return;
    float acc = 0.f;
    const int s0 = b * 64;
    for (int s = s0; s < s0 + 64; s++) {
        float cf = g_coeff[s];
        float v  = (j < H_DIM) ? g_hidden[s * H_DIM + j] : g_m[s * D_DIM + (j - H_DIM)];
        acc = fmaf(cf, v, acc);
    }
    g_partial[b * G4 + j] = acc;
}

// ---------------- K6: final sum + output heads ----------------
__global__ __launch_bounds__(608)
void final_kernel(const float* __restrict__ W_emo, const float* __restrict__ b_emo,
                  const float* __restrict__ W_sent, const float* __restrict__ b_sent,
                  float* __restrict__ out) {
    __shared__ float HH[G4];
    const int j = threadIdx.x;
    if (j < G4) {
        float a = 0.f;
        for (int b = 0; b < 64; b++) a += g_partial[b * G4 + j];
        HH[j] = a;
    }
    __syncthreads();
    if (j < 8) {
        float a = b_emo[j];
        for (int k = 0; k < G4; k++) a = fmaf(HH[k], W_emo[k * 8 + j], a);
        out[j] = a;
    } else if (j == 8) {
        float a = b_sent[0];
        for (int k = 0; k < G4; k++) a = fmaf(HH[k], W_sent[k], a);
        out[8] = a;
    }
}

// ---------------- launch ----------------
extern "C" void kernel_launch(void* const* d_in, const int* in_sizes, int n_in,
                              void* d_out, int out_size) {
    const int*   sent   = (const int*)d_in[0];
    const int*   syn    = (const int*)d_in[1];
    const float* E      = (const float*)d_in[2];
    const float* W_f    = (const float*)d_in[3];
    const float* U_f    = (const float*)d_in[4];
    const float* b_f    = (const float*)d_in[5];
    const float* W_b    = (const float*)d_in[6];
    const float* U_b    = (const float*)d_in[7];
    const float* b_b    = (const float*)d_in[8];
    const float* W_p    = (const float*)d_in[9];
    const float* b_p    = (const float*)d_in[10];
    const float* W_s    = (const float*)d_in[11];
    const float* b_s    = (const float*)d_in[12];
    const float* W_emo  = (const float*)d_in[13];
    const float* b_emo  = (const float*)d_in[14];
    const float* W_sent = (const float*)d_in[15];
    const float* b_sent = (const float*)d_in[16];
    float* out = (float*)d_out;

    dummy_kernel<<<1, 32>>>();                         // keep ncu capture slot
    dummy_kernel<<<1, 32>>>();                         // on lstm_kernel
    dim3 gxw(S_LEN / 16, 2);
    xw_kernel<<<gxw, 608>>>(sent, E, W_f, b_f, W_b, b_b);
    lstm_kernel<<<4, 608>>>(U_f, U_b);                 // 2 clusters x 2 CTAs, flight-hiding order
    attdense_kernel<<<S_LEN / 16, 320>>>(W_p, b_p);
    attn_kernel<<<S_LEN, 320>>>(syn, E, W_s, b_s);
    reduce1_kernel<<<64, 608>>>();
    final_kernel<<<1, 608>>>(W_emo, b_emo, W_sent, b_sent, out);
}

// round 12
// speedup vs baseline: 1.1991x; 1.1991x over previous
#include <cuda_runtime.h>

#define S_LEN 4096
#define D_DIM 300
#define H_DIM 300
#define HU    150
#define G4    600   // 4*HU

// ---------------- scratch (static device globals; no allocation) ----------------
__device__ float g_xW[2][S_LEN * G4];        // x@W + b, per direction (bwd pre-reversed)
__device__ float g_hidden[S_LEN * H_DIM];    // [S,300]: cols 0..149 fwd, 150..299 bwd
__device__ float g_attout[S_LEN * H_DIM];    // hidden @ W_p + b_p
__device__ float g_m[S_LEN * D_DIM];         // attention m vectors
__device__ float g_coeff[S_LEN];             // secondary attention coeffs
__device__ float g_partial[64 * G4];         // deterministic reduction partials

// ---------------- helpers ----------------
__device__ __forceinline__ unsigned long long ffma2(unsigned long long a,
                                                    unsigned long long b,
                                                    unsigned long long c) {
    unsigned long long d;
    asm("fma.rn.f32x2 %0, %1, %2, %3;" : "=l"(d) : "l"(a), "l"(b), "l"(c));
    return d;
}
__device__ __forceinline__ unsigned long long pack2(float lo, float hi) {
    unsigned long long p;
    asm("mov.b64 %0, {%1, %2};" : "=l"(p) : "f"(lo), "f"(hi));
    return p;
}
__device__ __forceinline__ void unpack2(unsigned long long v, float& lo, float& hi) {
    asm("mov.b64 {%0, %1}, %2;" : "=f"(lo), "=f"(hi) : "l"(v));
}
__device__ __forceinline__ void cluster_sync_() {
    asm volatile("barrier.cluster.arrive.aligned;" ::: "memory");
    asm volatile("barrier.cluster.wait.aligned;" ::: "memory");
}
__device__ __forceinline__ void bar640_() {
    asm volatile("bar.sync 0, 640;" ::: "memory");
}
__device__ __forceinline__ float ex2f_(float x) {
    float y; asm("ex2.approx.f32 %0, %1;" : "=f"(y) : "f"(x)); return y;
}
__device__ __forceinline__ float rcpf_(float x) {
    float y; asm("rcp.approx.f32 %0, %1;" : "=f"(y) : "f"(x)); return y;
}
// sigmoid via ex2/rcp approx: rel err ~1e-7 (far inside 1e-3 budget)
__device__ __forceinline__ float sigmoid_fast(float x) {
    return rcpf_(1.0f + ex2f_(-1.4426950408889634f * x));
}
__device__ __forceinline__ float tanh_fast(float x) {
    return fmaf(2.0f, sigmoid_fast(2.0f * x), -1.0f);
}

// ---------------- K0: no-op (keeps ncu's capture window on lstm_kernel) ----------------
__global__ void dummy_kernel() {}

// ---------------- K1: xW = gather(emb) @ W_dir + b_dir (bwd rows pre-reversed) ----------------
__global__ __launch_bounds__(608, 2)
void xw_kernel(const int* __restrict__ sent, const float* __restrict__ E,
               const float* __restrict__ W_f, const float* __restrict__ b_f,
               const float* __restrict__ W_b, const float* __restrict__ b_b) {
    const int dir = blockIdx.y;
    const int s0  = blockIdx.x * 16;
    const float* __restrict__ W  = dir ? W_b : W_f;
    const float* __restrict__ bv = dir ? b_b : b_f;
    __shared__ float esm[16 * D_DIM];
    const int tid = threadIdx.x;
    for (int i = tid; i < 16 * D_DIM; i += 608) {
        int r = i / D_DIM, k = i - r * D_DIM;
        int srow = dir ? (S_LEN - 1 - (s0 + r)) : (s0 + r);
        esm[i] = E[(long long)sent[srow] * D_DIM + k];
    }
    __syncthreads();
    const int j = tid;
    if (j < G4) {
        float acc[16];
#pragma unroll
        for (int r = 0; r < 16; r++) acc[r] = 0.f;
        for (int k = 0; k < D_DIM; k++) {
            float w = W[k * G4 + j];
#pragma unroll
            for (int r = 0; r < 16; r++) acc[r] = fmaf(esm[r * D_DIM + k], w, acc[r]);
        }
        float bb = bv[j];
#pragma unroll
        for (int r = 0; r < 16; r++) g_xW[dir][(s0 + r) * G4 + j] = acc[r] + bb;
    }
}

// ---------------- K2: persistent biLSTM. 2 clusters of 2 CTAs (one cluster/dir). ----------------
// 640 threads = 19 compute warps (R9 mapping: cell=tid>>3, gate=(tid>>1)&3, K-half=tid&1;
// both half-dots run CONCURRENTLY after the bar) + 1 POLLER warp (tids 608-639).
// Poller overlap: while compute runs step t, the poller spins on the peer's tag-t packets
// (in flight during our tail) and stages them into stage[(t+1)&1]; ONE bar.sync(640) per
// step joins them. Compute warps never poll -> DSMEM flight/spin off the critical path.
__global__ void __cluster_dims__(2, 1, 1) __launch_bounds__(640, 1)
lstm_kernel(const float* __restrict__ U_f, const float* __restrict__ U_b) {
    const int dir = blockIdx.x >> 1;
    unsigned rank; asm("mov.u32 %0, %%cluster_ctarank;" : "=r"(rank));
    const int tid = threadIdx.x;
    const float* __restrict__ U  = dir ? U_b : U_f;
    const float* __restrict__ xW = g_xW[dir];

    __shared__ __align__(16) float own_h[2][76];               // local h, slot 75 = pad
    __shared__ __align__(16) float stage[2][76];               // staged peer h values
    __shared__ __align__(8)  unsigned long long pkt[2][76];    // {val lo32, tag hi32}, remote-written

    for (int i = tid; i < 152; i += 640) ((float*)own_h)[i] = 0.f;
    for (int i = tid; i < 152; i += 640) ((float*)stage)[i] = 0.f;
    for (int i = tid; i < 76; i += 640) {
        pkt[0][i] = 0xFFFFFFFE00000000ull;   // sentinel (never matches a tag)
        pkt[1][i] = 0xFFFFFFFE00000000ull;
    }
    __syncthreads();

    unsigned pk_base = (unsigned)__cvta_generic_to_shared(&pkt[0][0]);
    unsigned peer = rank ^ 1u;
    unsigned r_pk;
    asm("mapa.shared::cluster.u32 %0, %1, %2;" : "=r"(r_pk) : "r"(pk_base), "r"(peer));

    cluster_sync_();   // init (incl. pkt sentinels) visible cluster-wide before any writes

    if (tid >= 608) {
        // ---------------- POLLER WARP ----------------
        const int lane = tid - 608;
        // slots this lane owns: lane, lane+32, lane+64 (skip >=75)
        for (int u = 0; u < S_LEN; u++) {
            if (u < S_LEN - 1) {
                const int b = (u + 1) & 1;           // packets tag u live in pkt[b]
                const unsigned want = (unsigned)u;
#pragma unroll
                for (int k = 0; k < 3; k++) {
                    int s = lane + 32 * k;
                    if (s < 75) {
                        unsigned lo, hi;
                        unsigned ad = pk_base + ((unsigned)b * 76u + (unsigned)s) * 8u;
                        do {
                            asm volatile("ld.volatile.shared.v2.u32 {%0, %1}, [%2];"
                                         : "=r"(lo), "=r"(hi) : "r"(ad));
                        } while (hi != want);
                        stage[b][s] = __uint_as_float(lo);
                    }
                }
            }
            bar640_();   // joins compute's end-of-step bar; publishes stage
        }
    } else {
        // ---------------- COMPUTE WARPS (R9 mapping) ----------------
        const bool active = tid < 600;
        const int hf   = tid & 1;                   // K-half: 0 = own cells, 1 = peer cells
        const int g    = (tid >> 1) & 3;            // gate i,f,g,o
        const int mloc = tid >> 3;                  // 0..74 when active
        const int m    = (int)rank * 75 + (active ? mloc : 0);
        const int j    = g * HU + m;                // column in [0,600)
        const int prank = 1 - (int)rank;
        const int hb   = hf ? prank * 75 : (int)rank * 75;

        // 38 u64 of U for this thread's K-half (pad pair index 75 -> zero weight)
        unsigned long long u64[38];
#pragma unroll
        for (int s = 0; s < 38; s++) {
            int k0 = 2 * s, k1 = 2 * s + 1;
            float w0 = (active && k0 < 75) ? U[(hb + k0) * G4 + j] : 0.f;
            float w1 = (active && k1 < 75) ? U[(hb + k1) * G4 + j] : 0.f;
            u64[s] = pack2(w0, w1);
        }

        float c = 0.f;
        float xw_cur = (active && hf == 0) ? xW[j] : 0.f;
        const bool is_writer = active && (tid & 7) == 0;

        for (int t = 0; t < S_LEN; t++) {
            const int p  = t & 1;        // read buffer (stage/own_h published by prev bar)
            const int nb = p ^ 1;        // write buffer

            float xw_next = 0.f;
            if (active && hf == 0 && t + 1 < S_LEN) xw_next = xW[(t + 1) * G4 + j];

            // half dot product: hf0 over own_h[p], hf1 over stage[p] — CONCURRENT
            unsigned long long a0 = pack2(xw_cur, 0.f), a1 = 0ull;
            const ulonglong2* hp = (const ulonglong2*)(hf ? &stage[p][0] : &own_h[p][0]);
#pragma unroll
            for (int q = 0; q < 19; q++) {
                ulonglong2 v = hp[q];
                a0 = ffma2(u64[2 * q], v.x, a0);
                a1 = ffma2(u64[2 * q + 1], v.y, a1);
            }
            float x0, x1, y0, y1;
            unpack2(a0, x0, x1); unpack2(a1, y0, y1);
            float zh = (x0 + x1) + (y0 + y1);

            // combine K-halves, activations, gate exchange in the aligned 8-lane cell group
            float zfull = zh + __shfl_xor_sync(0xffffffffu, zh, 1);
            float act = (g == 2) ? tanh_fast(zfull) : sigmoid_fast(zfull);
            float sf = __shfl_xor_sync(0xffffffffu, act, 2);   // writer receives f
            float sg = __shfl_xor_sync(0xffffffffu, act, 4);   // writer receives g
            float so = __shfl_xor_sync(0xffffffffu, act, 6);   // writer receives o

            if (is_writer) {
                c = fmaf(sf, c, act * sg);                     // c = f*c + i*g
                float hv = so * tanh_fast(c);
                if (t + 1 < S_LEN) {                           // remote: ONE weak 8B store
                    unsigned long long pk = ((unsigned long long)(unsigned)t << 32)
                                          | (unsigned long long)__float_as_uint(hv);
                    unsigned ra = r_pk + ((unsigned)nb * 76u + (unsigned)mloc) * 8u;
                    asm volatile("st.shared::cluster.u64 [%0], %1;" :: "r"(ra), "l"(pk) : "memory");
                }
                own_h[nb][mloc] = hv;                          // local half
                int row = dir ? (S_LEN - 1 - t) : t;
                g_hidden[row * H_DIM + dir * HU + m] = hv;
            }
            bar640_();   // publishes own_h[nb] + stage[nb] (poller) for next step
            xw_cur = xw_next;
        }
    }
    cluster_sync_();   // release our last remote stores before CTA teardown
}

// ---------------- K3: attout = hidden @ W_p + b_p ----------------
__global__ __launch_bounds__(320, 2)
void attdense_kernel(const float* __restrict__ W_p, const float* __restrict__ b_p) {
    const int s0 = blockIdx.x * 16;
    __shared__ float hsm[16 * H_DIM];
    const int tid = threadIdx.x;
    for (int i = tid; i < 16 * H_DIM; i += 320) hsm[i] = g_hidden[s0 * H_DIM + i];
    __syncthreads();
    const int j = tid;
    if (j < H_DIM) {
        float acc[16];
#pragma unroll
        for (int r = 0; r < 16; r++) acc[r] = 0.f;
        for (int k = 0; k < H_DIM; k++) {
            float w = W_p[k * H_DIM + j];
#pragma unroll
            for (int r = 0; r < 16; r++) acc[r] = fmaf(hsm[r * H_DIM + k], w, acc[r]);
        }
        float bb = b_p[j];
#pragma unroll
        for (int r = 0; r < 16; r++) g_attout[(s0 + r) * H_DIM + j] = acc[r] + bb;
    }
}

// ---------------- K4: per-word synonym attention + secondary coeff ----------------
__device__ __forceinline__ float block_reduce_320(float v, float* red, int lane, int wid) {
#pragma unroll
    for (int off = 16; off; off >>= 1) v += __shfl_down_sync(0xffffffffu, v, off);
    __syncthreads();
    if (lane == 0) red[wid] = v;
    __syncthreads();
    float t = 0.f;
#pragma unroll
    for (int w = 0; w < 10; w++) t += red[w];
    return t;
}

__global__ __launch_bounds__(320)
void attn_kernel(const int* __restrict__ syn_idx, const float* __restrict__ E,
                 const float* __restrict__ W_s, const float* __restrict__ b_s) {
    const int s   = blockIdx.x;
    const int tid = threadIdx.x;
    const int lane = tid & 31, wid = tid >> 5;
    __shared__ float red[10];
    const bool active = tid < D_DIM;

    float od = 0.f, hd = 0.f;
    float ev[4] = {0.f, 0.f, 0.f, 0.f};
    if (active) {
        od = g_attout[s * H_DIM + tid];
        hd = g_hidden[s * H_DIM + tid];
#pragma unroll
        for (int k = 0; k < 4; k++)
            ev[k] = E[(long long)syn_idx[s * 4 + k] * D_DIM + tid];
    }
    float sc[4];
#pragma unroll
    for (int k = 0; k < 4; k++) {
        float dot = block_reduce_320(od * ev[k], red, lane, wid);
        sc[k] = expf(dot);
    }
    float md = sc[0] * ev[0] + sc[1] * ev[1] + sc[2] * ev[2] + sc[3] * ev[3];
    if (active) g_m[s * D_DIM + tid] = md;
    float cv = active ? (hd * W_s[tid] + md * W_s[D_DIM + tid]) : 0.f;
    float tot = block_reduce_320(cv, red, lane, wid);
    if (tid == 0) g_coeff[s] = expf(tanhf(tot + b_s[0]));
}

// ---------------- K5: deterministic partial reduction of coeff * h_hat ----------------
__global__ __launch_bounds__(608)
void reduce1_kernel() {
    const int b = blockIdx.x;
    const int j = threadIdx.x;
    if (j >= G4) return;
    float acc = 0.f;
    const int s0 = b * 64;
    for (int s = s0; s < s0 + 64; s++) {
        float cf = g_coeff[s];
        float v  = (j < H_DIM) ? g_hidden[s * H_DIM + j] : g_m[s * D_DIM + (j - H_DIM)];
        acc = fmaf(cf, v, acc);
    }
    g_partial[b * G4 + j] = acc;
}

// ---------------- K6: final sum + output heads ----------------
__global__ __launch_bounds__(608)
void final_kernel(const float* __restrict__ W_emo, const float* __restrict__ b_emo,
                  const float* __restrict__ W_sent, const float* __restrict__ b_sent,
                  float* __restrict__ out) {
    __shared__ float HH[G4];
    const int j = threadIdx.x;
    if (j < G4) {
        float a = 0.f;
        for (int b = 0; b < 64; b++) a += g_partial[b * G4 + j];
        HH[j] = a;
    }
    __syncthreads();
    if (j < 8) {
        float a = b_emo[j];
        for (int k = 0; k < G4; k++) a = fmaf(HH[k], W_emo[k * 8 + j], a);
        out[j] = a;
    } else if (j == 8) {
        float a = b_sent[0];
        for (int k = 0; k < G4; k++) a = fmaf(HH[k], W_sent[k], a);
        out[8] = a;
    }
}

// ---------------- launch ----------------
extern "C" void kernel_launch(void* const* d_in, const int* in_sizes, int n_in,
                              void* d_out, int out_size) {
    const int*   sent   = (const int*)d_in[0];
    const int*   syn    = (const int*)d_in[1];
    const float* E      = (const float*)d_in[2];
    const float* W_f    = (const float*)d_in[3];
    const float* U_f    = (const float*)d_in[4];
    const float* b_f    = (const float*)d_in[5];
    const float* W_b    = (const float*)d_in[6];
    const float* U_b    = (const float*)d_in[7];
    const float* b_b    = (const float*)d_in[8];
    const float* W_p    = (const float*)d_in[9];
    const float* b_p    = (const float*)d_in[10];
    const float* W_s    = (const float*)d_in[11];
    const float* b_s    = (const float*)d_in[12];
    const float* W_emo  = (const float*)d_in[13];
    const float* b_emo  = (const float*)d_in[14];
    const float* W_sent = (const float*)d_in[15];
    const float* b_sent = (const float*)d_in[16];
    float* out = (float*)d_out;

    dummy_kernel<<<1, 32>>>();                         // keep ncu capture slot
    dummy_kernel<<<1, 32>>>();                         // on lstm_kernel
    dim3 gxw(S_LEN / 16, 2);
    xw_kernel<<<gxw, 608>>>(sent, E, W_f, b_f, W_b, b_b);
    lstm_kernel<<<4, 640>>>(U_f, U_b);                 // 2 clusters x 2 CTAs + poller warp
    attdense_kernel<<<S_LEN / 16, 320>>>(W_p, b_p);
    attn_kernel<<<S_LEN, 320>>>(syn, E, W_s, b_s);
    reduce1_kernel<<<64, 608>>>();
    final_kernel<<<1, 608>>>(W_emo, b_emo, W_sent, b_sent, out);
}

// round 13
// speedup vs baseline: 1.5343x; 1.2795x over previous
#include <cuda_runtime.h>

#define S_LEN 4096
#define D_DIM 300
#define H_DIM 300
#define HU    150
#define G4    600   // 4*HU

// ---------------- scratch (static device globals; no allocation) ----------------
__device__ float g_xW[2][S_LEN * G4];        // x@W + b, per direction (bwd pre-reversed)
__device__ float g_hidden[S_LEN * H_DIM];    // [S,300]: cols 0..149 fwd, 150..299 bwd
__device__ float g_attout[S_LEN * H_DIM];    // hidden @ W_p + b_p
__device__ float g_m[S_LEN * D_DIM];         // attention m vectors
__device__ float g_coeff[S_LEN];             // secondary attention coeffs
__device__ float g_partial[64 * G4];         // deterministic reduction partials

// ---------------- helpers ----------------
__device__ __forceinline__ unsigned long long ffma2(unsigned long long a,
                                                    unsigned long long b,
                                                    unsigned long long c) {
    unsigned long long d;
    asm("fma.rn.f32x2 %0, %1, %2, %3;" : "=l"(d) : "l"(a), "l"(b), "l"(c));
    return d;
}
__device__ __forceinline__ unsigned long long pack2(float lo, float hi) {
    unsigned long long p;
    asm("mov.b64 %0, {%1, %2};" : "=l"(p) : "f"(lo), "f"(hi));
    return p;
}
__device__ __forceinline__ void unpack2(unsigned long long v, float& lo, float& hi) {
    asm("mov.b64 {%0, %1}, %2;" : "=f"(lo), "=f"(hi) : "l"(v));
}
__device__ __forceinline__ void cluster_sync_() {
    asm volatile("barrier.cluster.arrive.aligned;" ::: "memory");
    asm volatile("barrier.cluster.wait.aligned;" ::: "memory");
}
__device__ __forceinline__ float ex2f_(float x) {
    float y; asm("ex2.approx.f32 %0, %1;" : "=f"(y) : "f"(x)); return y;
}
__device__ __forceinline__ float rcpf_(float x) {
    float y; asm("rcp.approx.f32 %0, %1;" : "=f"(y) : "f"(x)); return y;
}
// sigmoid via ex2/rcp approx: rel err ~1e-7 (far inside 1e-3 budget)
__device__ __forceinline__ float sigmoid_fast(float x) {
    return rcpf_(1.0f + ex2f_(-1.4426950408889634f * x));
}
__device__ __forceinline__ float tanh_fast(float x) {
    return fmaf(2.0f, sigmoid_fast(2.0f * x), -1.0f);
}

// ---------------- K0: no-op (keeps ncu's capture window on lstm_kernel) ----------------
__global__ void dummy_kernel() {}

// ---------------- K1: xW = gather(emb) @ W_dir + b_dir (bwd rows pre-reversed) ----------------
__global__ __launch_bounds__(608, 2)
void xw_kernel(const int* __restrict__ sent, const float* __restrict__ E,
               const float* __restrict__ W_f, const float* __restrict__ b_f,
               const float* __restrict__ W_b, const float* __restrict__ b_b) {
    const int dir = blockIdx.y;
    const int s0  = blockIdx.x * 16;
    const float* __restrict__ W  = dir ? W_b : W_f;
    const float* __restrict__ bv = dir ? b_b : b_f;
    __shared__ float esm[16 * D_DIM];
    const int tid = threadIdx.x;
    for (int i = tid; i < 16 * D_DIM; i += 608) {
        int r = i / D_DIM, k = i - r * D_DIM;
        int srow = dir ? (S_LEN - 1 - (s0 + r)) : (s0 + r);
        esm[i] = E[(long long)sent[srow] * D_DIM + k];
    }
    __syncthreads();
    const int j = tid;
    if (j < G4) {
        float acc[16];
#pragma unroll
        for (int r = 0; r < 16; r++) acc[r] = 0.f;
        for (int k = 0; k < D_DIM; k++) {
            float w = W[k * G4 + j];
#pragma unroll
            for (int r = 0; r < 16; r++) acc[r] = fmaf(esm[r * D_DIM + k], w, acc[r]);
        }
        float bb = bv[j];
#pragma unroll
        for (int r = 0; r < 16; r++) g_xW[dir][(s0 + r) * G4 + j] = acc[r] + bb;
    }
}

// ---------------- K2: persistent biLSTM. 2 clusters of 2 CTAs (one cluster/dir). ----------------
// R9 structure (best measured): 608 threads, thread = (cell=tid>>3, gate=(tid>>1)&3, K-half=tid&1),
// 38 u64 of U each; both half-dots run concurrently; checkers (tid&7==2) spin + stage; ONE bar.
// R13 compute surgery: 4 dot accumulators (shorter chain, de-correlated reg banks),
// branch-free activation via per-lane (A,B,C) constants, remote send first in writer tail.
__global__ void __cluster_dims__(2, 1, 1) __launch_bounds__(608, 1)
lstm_kernel(const float* __restrict__ U_f, const float* __restrict__ U_b) {
    const int dir = blockIdx.x >> 1;
    unsigned rank; asm("mov.u32 %0, %%cluster_ctarank;" : "=r"(rank));
    const int tid = threadIdx.x;
    const float* __restrict__ U  = dir ? U_b : U_f;
    const float* __restrict__ xW = g_xW[dir];

    __shared__ __align__(16) float own_h[2][76];               // local h, slot 75 = pad
    __shared__ __align__(16) float stage[2][76];               // validated peer h values
    __shared__ __align__(8)  unsigned long long pkt[2][76];    // {val lo32, tag hi32}, remote-written

    for (int i = tid; i < 152; i += 608) ((float*)own_h)[i] = 0.f;
    for (int i = tid; i < 152; i += 608) ((float*)stage)[i] = 0.f;
    for (int i = tid; i < 76; i += 608) {
        pkt[0][i] = 0xFFFFFFFF00000000ull;   // tag -1, val 0 (consumed at t=0)
        pkt[1][i] = 0xFFFFFFFE00000000ull;   // tag -2 (never matches until written)
    }
    __syncthreads();

    const bool active = tid < 600;
    const int hf   = tid & 1;                   // K-half: 0 = own cells, 1 = peer cells
    const int g    = (tid >> 1) & 3;            // gate i,f,g,o
    const int mloc = tid >> 3;                  // 0..74 when active
    const int m    = (int)rank * 75 + (active ? mloc : 0);
    const int j    = g * HU + m;                // column in [0,600)
    const int prank = 1 - (int)rank;
    const int hb   = hf ? prank * 75 : (int)rank * 75;   // U row base for this half

    // branch-free activation constants: sigma gates (A=1,C=0,B=-1.4427), tanh gate g==2
    // (tanh(z) = 2*sigma(2z)-1 -> A=2, C=-1, B=-2.8854). act = fmaf(A, rcp(1+ex2(B*z)), C)
    const float actA = (g == 2) ? 2.f : 1.f;
    const float actC = (g == 2) ? -1.f : 0.f;
    const float actB = (g == 2) ? -2.8853900817779268f : -1.4426950408889634f;

    // 38 u64 of U for this thread's K-half (pad pair index 75 -> zero weight)
    unsigned long long u64[38];
#pragma unroll
    for (int s = 0; s < 38; s++) {
        int k0 = 2 * s, k1 = 2 * s + 1;
        float w0 = (active && k0 < 75) ? U[(hb + k0) * G4 + j] : 0.f;
        float w1 = (active && k1 < 75) ? U[(hb + k1) * G4 + j] : 0.f;
        u64[s] = pack2(w0, w1);
    }

    // addresses: local pkt (for checker spin) and remote pkt in peer CTA (for writer push)
    unsigned pk_base = (unsigned)__cvta_generic_to_shared(&pkt[0][0]);
    unsigned peer = rank ^ 1u;
    unsigned r_pk;
    asm("mapa.shared::cluster.u32 %0, %1, %2;" : "=r"(r_pk) : "r"(pk_base), "r"(peer));

    cluster_sync_();   // init (incl. pkt sentinels) visible cluster-wide before any writes

    float c = 0.f;
    float xw_cur = (active && hf == 0) ? xW[j] : 0.f;   // xW added once, on hf0 lane
    const bool is_checker = active && (tid & 7) == 2;
    const bool is_writer  = active && (tid & 7) == 0;

    for (int t = 0; t < S_LEN; t++) {
        const int p  = t & 1;        // read buffer
        const int nb = p ^ 1;        // write buffer

        // prefetch next xW row (hf0 lanes; consumed next step)
        float xw_next = 0.f;
        if (active && hf == 0 && t + 1 < S_LEN) xw_next = xW[(t + 1) * G4 + j];

        // checkers: spin until {h, tag=t-1} landed (usually already has), stage value
        if (is_checker) {
            unsigned lo, hi;
            unsigned ad = pk_base + ((unsigned)p * 76u + (unsigned)mloc) * 8u;
            const unsigned want = (unsigned)(t - 1);
            do {
                asm volatile("ld.volatile.shared.v2.u32 {%0, %1}, [%2];"
                             : "=r"(lo), "=r"(hi) : "r"(ad));
            } while (hi != want);
            stage[p][mloc] = __uint_as_float(lo);
        }
        __syncthreads();   // publishes stage[p]; orders prev step's own_h[p] writes

        // half dot product (4 accumulators): hf0 over own_h[p], hf1 over stage[p] — CONCURRENT
        unsigned long long a0 = pack2(xw_cur, 0.f), a1 = 0ull, a2 = 0ull, a3 = 0ull;
        const ulonglong2* hp = (const ulonglong2*)(hf ? &stage[p][0] : &own_h[p][0]);
#pragma unroll
        for (int q = 0; q < 19; q++) {
            ulonglong2 v = hp[q];
            if (q & 1) { a2 = ffma2(u64[2 * q], v.x, a2); a3 = ffma2(u64[2 * q + 1], v.y, a3); }
            else       { a0 = ffma2(u64[2 * q], v.x, a0); a1 = ffma2(u64[2 * q + 1], v.y, a1); }
        }
        float x0, x1, y0, y1, z0, z1, w0, w1;
        unpack2(a0, x0, x1); unpack2(a1, y0, y1);
        unpack2(a2, z0, z1); unpack2(a3, w0, w1);
        float zh = ((x0 + x1) + (y0 + y1)) + ((z0 + z1) + (w0 + w1));

        // combine K-halves; branch-free activation; gate exchange in aligned 8-lane cell group
        float zfull = zh + __shfl_xor_sync(0xffffffffu, zh, 1);
        float act = fmaf(actA, rcpf_(1.0f + ex2f_(actB * zfull)), actC);
        float sf = __shfl_xor_sync(0xffffffffu, act, 2);   // writer receives f
        float sg = __shfl_xor_sync(0xffffffffu, act, 4);   // writer receives g
        float so = __shfl_xor_sync(0xffffffffu, act, 6);   // writer receives o

        if (is_writer) {
            c = fmaf(sf, c, act * sg);                     // c = f*c + i*g
            float hv = so * tanh_fast(c);
            if (t + 1 < S_LEN) {                           // remote FIRST: on mutual critical path
                unsigned long long pk = ((unsigned long long)(unsigned)t << 32)
                                      | (unsigned long long)__float_as_uint(hv);
                unsigned ra = r_pk + ((unsigned)nb * 76u + (unsigned)mloc) * 8u;
                asm volatile("st.shared::cluster.u64 [%0], %1;" :: "r"(ra), "l"(pk) : "memory");
            }
            own_h[nb][mloc] = hv;                          // local half
            int row = dir ? (S_LEN - 1 - t) : t;
            g_hidden[row * H_DIM + dir * HU + m] = hv;     // fire-and-forget
        }
        xw_cur = xw_next;
        // no end-of-step barrier: next step's __syncthreads orders own_h[nb] for all readers
    }
    cluster_sync_();   // release our last remote stores before CTA teardown
}

// ---------------- K3: attout = hidden @ W_p + b_p ----------------
__global__ __launch_bounds__(320, 2)
void attdense_kernel(const float* __restrict__ W_p, const float* __restrict__ b_p) {
    const int s0 = blockIdx.x * 16;
    __shared__ float hsm[16 * H_DIM];
    const int tid = threadIdx.x;
    for (int i = tid; i < 16 * H_DIM; i += 320) hsm[i] = g_hidden[s0 * H_DIM + i];
    __syncthreads();
    const int j = tid;
    if (j < H_DIM) {
        float acc[16];
#pragma unroll
        for (int r = 0; r < 16; r++) acc[r] = 0.f;
        for (int k = 0; k < H_DIM; k++) {
            float w = W_p[k * H_DIM + j];
#pragma unroll
            for (int r = 0; r < 16; r++) acc[r] = fmaf(hsm[r * H_DIM + k], w, acc[r]);
        }
        float bb = b_p[j];
#pragma unroll
        for (int r = 0; r < 16; r++) g_attout[(s0 + r) * H_DIM + j] = acc[r] + bb;
    }
}

// ---------------- K4: per-word synonym attention + secondary coeff ----------------
__device__ __forceinline__ float block_reduce_320(float v, float* red, int lane, int wid) {
#pragma unroll
    for (int off = 16; off; off >>= 1) v += __shfl_down_sync(0xffffffffu, v, off);
    __syncthreads();
    if (lane == 0) red[wid] = v;
    __syncthreads();
    float t = 0.f;
#pragma unroll
    for (int w = 0; w < 10; w++) t += red[w];
    return t;
}

__global__ __launch_bounds__(320)
void attn_kernel(const int* __restrict__ syn_idx, const float* __restrict__ E,
                 const float* __restrict__ W_s, const float* __restrict__ b_s) {
    const int s   = blockIdx.x;
    const int tid = threadIdx.x;
    const int lane = tid & 31, wid = tid >> 5;
    __shared__ float red[10];
    const bool active = tid < D_DIM;

    float od = 0.f, hd = 0.f;
    float ev[4] = {0.f, 0.f, 0.f, 0.f};
    if (active) {
        od = g_attout[s * H_DIM + tid];
        hd = g_hidden[s * H_DIM + tid];
#pragma unroll
        for (int k = 0; k < 4; k++)
            ev[k] = E[(long long)syn_idx[s * 4 + k] * D_DIM + tid];
    }
    float sc[4];
#pragma unroll
    for (int k = 0; k < 4; k++) {
        float dot = block_reduce_320(od * ev[k], red, lane, wid);
        sc[k] = expf(dot);
    }
    float md = sc[0] * ev[0] + sc[1] * ev[1] + sc[2] * ev[2] + sc[3] * ev[3];
    if (active) g_m[s * D_DIM + tid] = md;
    float cv = active ? (hd * W_s[tid] + md * W_s[D_DIM + tid]) : 0.f;
    float tot = block_reduce_320(cv, red, lane, wid);
    if (tid == 0) g_coeff[s] = expf(tanhf(tot + b_s[0]));
}

// ---------------- K5: deterministic partial reduction of coeff * h_hat ----------------
__global__ __launch_bounds__(608)
void reduce1_kernel() {
    const int b = blockIdx.x;
    const int j = threadIdx.x;
    if (j >= G4) return;
    float acc = 0.f;
    const int s0 = b * 64;
    for (int s = s0; s < s0 + 64; s++) {
        float cf = g_coeff[s];
        float v  = (j < H_DIM) ? g_hidden[s * H_DIM + j] : g_m[s * D_DIM + (j - H_DIM)];
        acc = fmaf(cf, v, acc);
    }
    g_partial[b * G4 + j] = acc;
}

// ---------------- K6: final sum + output heads ----------------
__global__ __launch_bounds__(608)
void final_kernel(const float* __restrict__ W_emo, const float* __restrict__ b_emo,
                  const float* __restrict__ W_sent, const float* __restrict__ b_sent,
                  float* __restrict__ out) {
    __shared__ float HH[G4];
    const int j = threadIdx.x;
    if (j < G4) {
        float a = 0.f;
        for (int b = 0; b < 64; b++) a += g_partial[b * G4 + j];
        HH[j] = a;
    }
    __syncthreads();
    if (j < 8) {
        float a = b_emo[j];
        for (int k = 0; k < G4; k++) a = fmaf(HH[k], W_emo[k * 8 + j], a);
        out[j] = a;
    } else if (j == 8) {
        float a = b_sent[0];
        for (int k = 0; k < G4; k++) a = fmaf(HH[k], W_sent[k], a);
        out[8] = a;
    }
}

// ---------------- launch ----------------
extern "C" void kernel_launch(void* const* d_in, const int* in_sizes, int n_in,
                              void* d_out, int out_size) {
    const int*   sent   = (const int*)d_in[0];
    const int*   syn    = (const int*)d_in[1];
    const float* E      = (const float*)d_in[2];
    const float* W_f    = (const float*)d_in[3];
    const float* U_f    = (const float*)d_in[4];
    const float* b_f    = (const float*)d_in[5];
    const float* W_b    = (const float*)d_in[6];
    const float* U_b    = (const float*)d_in[7];
    const float* b_b    = (const float*)d_in[8];
    const float* W_p    = (const float*)d_in[9];
    const float* b_p    = (const float*)d_in[10];
    const float* W_s    = (const float*)d_in[11];
    const float* b_s    = (const float*)d_in[12];
    const float* W_emo  = (const float*)d_in[13];
    const float* b_emo  = (const float*)d_in[14];
    const float* W_sent = (const float*)d_in[15];
    const float* b_sent = (const float*)d_in[16];
    float* out = (float*)d_out;

    dummy_kernel<<<1, 32>>>();                         // keep ncu capture slot
    dummy_kernel<<<1, 32>>>();                         // on lstm_kernel
    dim3 gxw(S_LEN / 16, 2);
    xw_kernel<<<gxw, 608>>>(sent, E, W_f, b_f, W_b, b_b);
    lstm_kernel<<<4, 608>>>(U_f, U_b);                 // R9 structure + compute surgery
    attdense_kernel<<<S_LEN / 16, 320>>>(W_p, b_p);
    attn_kernel<<<S_LEN, 320>>>(syn, E, W_s, b_s);
    reduce1_kernel<<<64, 608>>>();
    final_kernel<<<1, 608>>>(W_emo, b_emo, W_sent, b_sent, out);
}